// round 1
// baseline (speedup 1.0000x reference)
#include <cuda_runtime.h>

#define BB 2
#define NN 65536
#define KK 16
#define DD 32

// Scratch (device globals; no allocation allowed)
__device__ float4 g_pre4[BB * NN * 8];   // pre[b][n][32] as float4 rows (16 MB, L2-resident)
__device__ float  g_tnetmax[BB * 64];
__device__ float  g_tmat[BB * 9];
__device__ int    g_idx64;               // 1 if neigh_idx is int64, else 0

// ---------------------------------------------------------------------------
// K0: reset the TNet max accumulator; detect neigh_idx dtype (int32 vs int64).
// int64 little-endian with values < 2^31 has all odd 32-bit words == 0.
// ---------------------------------------------------------------------------
__global__ void k_init(const int* __restrict__ nidx) {
    int t = threadIdx.x;
    if (t < BB * 64) g_tnetmax[t] = 0.f;
    if (t == 0) {
        int z = 0;
#pragma unroll
        for (int i = 1; i < 16; i += 2) z |= nidx[i];
        g_idx64 = (z == 0) ? 1 : 0;
    }
}

// ---------------------------------------------------------------------------
// K1: TNet pointwise 3->16->64 + exact max-reduction over N per batch.
// ReLU outputs are >= 0, so float max == int-bit max (atomicMax on int bits).
// ---------------------------------------------------------------------------
__global__ void __launch_bounds__(256) k_tnet_reduce(
    const float* __restrict__ xyz,
    const float* __restrict__ tW1, const float* __restrict__ ts1, const float* __restrict__ tb1,
    const float* __restrict__ tW2, const float* __restrict__ ts2, const float* __restrict__ tb2)
{
    __shared__ float sW1[48], sS1[16], sB1[16];
    __shared__ float sW2[1024], sS2[64], sB2[64];
    __shared__ int   smax[64];
    int t = threadIdx.x;
    for (int i = t; i < 1024; i += 256) sW2[i] = tW2[i];
    if (t < 48) sW1[t] = tW1[t];
    if (t < 16) { sS1[t] = ts1[t]; sB1[t] = tb1[t]; }
    if (t < 64) { sS2[t] = ts2[t]; sB2[t] = tb2[t]; smax[t] = 0; }
    __syncthreads();

    int gp = blockIdx.x * 256 + t;      // global point; 256 | 65536 -> b uniform per block
    int b  = gp >> 16;
    float x0 = xyz[gp * 3 + 0], x1 = xyz[gp * 3 + 1], x2 = xyz[gp * 3 + 2];

    float h1[16];
#pragma unroll
    for (int c = 0; c < 16; c++) {
        float a = x0 * sW1[c] + x1 * sW1[16 + c] + x2 * sW1[32 + c];
        h1[c] = fmaxf(a * sS1[c] + sB1[c], 0.f);
    }
    float h2[64];
#pragma unroll
    for (int c = 0; c < 64; c++) h2[c] = 0.f;
#pragma unroll
    for (int i = 0; i < 16; i++) {
        float v = h1[i];
#pragma unroll
        for (int c = 0; c < 64; c++) h2[c] += v * sW2[i * 64 + c];
    }
    int lane = t & 31;
#pragma unroll
    for (int c = 0; c < 64; c++) {
        float a = fmaxf(h2[c] * sS2[c] + sB2[c], 0.f);
#pragma unroll
        for (int off = 16; off; off >>= 1)
            a = fmaxf(a, __shfl_xor_sync(0xffffffffu, a, off));
        if (lane == 0) atomicMax(&smax[c], __float_as_int(a));
    }
    __syncthreads();
    if (t < 64) atomicMax((int*)&g_tnetmax[b * 64 + t], smax[t]);
}

// ---------------------------------------------------------------------------
// K2: TNet head: 64 -> 16 -> 9 (+ identity) -> 3x3 transform per batch.
// ---------------------------------------------------------------------------
__global__ void k_tnet_head(
    const float* __restrict__ tW3, const float* __restrict__ ts3, const float* __restrict__ tb3,
    const float* __restrict__ tW4, const float* __restrict__ tb4)
{
    __shared__ float h3s[16];
    int b = blockIdx.x, t = threadIdx.x;
    if (t < 16) {
        float a = 0.f;
        for (int i = 0; i < 64; i++) a += g_tnetmax[b * 64 + i] * tW3[i * 16 + t];
        h3s[t] = fmaxf(a * ts3[t] + tb3[t], 0.f);
    }
    __syncthreads();
    if (t < 9) {
        float a = 0.f;
        for (int i = 0; i < 16; i++) a += h3s[i] * tW4[i * 9 + t];
        a += tb4[t];
        if (t == 0 || t == 4 || t == 8) a += 1.0f;   // + eye(3)
        g_tmat[b * 9 + t] = a;
    }
}

// ---------------------------------------------------------------------------
// K3: fused per-point MLPs. Computes f_xyz (3), f_nei (32), then
// pre[b,n,:] = relu((f_nei @ W3[:32] + f_xyz @ W3[32:35]) * s3 + b3).
// This is the 16x FLOP-reduction trick: the W3 MLP depends only on the
// source point, so it moves OUT of the K-neighbor loop.
// ---------------------------------------------------------------------------
__global__ void __launch_bounds__(256) k_pointwise(
    const float* __restrict__ feature, const float* __restrict__ xyz,
    const float* __restrict__ W1, const float* __restrict__ s1, const float* __restrict__ b1,
    const float* __restrict__ W2, const float* __restrict__ s2, const float* __restrict__ b2,
    const float* __restrict__ W3, const float* __restrict__ s3, const float* __restrict__ b3)
{
    __shared__ float sW2[1024], sW3[1120];
    __shared__ float sS2[32], sB2[32], sS3[32], sB3[32];
    __shared__ float sW1[9], sTM[9], sS1[3], sB1[3];
    __shared__ float stage[256 * 33];    // padded rows -> conflict-free scatter
    int t   = threadIdx.x;
    int gp0 = blockIdx.x * 256;
    int b   = gp0 >> 16;
    for (int i = t; i < 1024; i += 256) sW2[i] = W2[i];
    for (int i = t; i < 1120; i += 256) sW3[i] = W3[i];
    if (t < 32) { sS2[t] = s2[t]; sB2[t] = b2[t]; sS3[t] = s3[t]; sB3[t] = b3[t]; }
    if (t < 9)  { sW1[t] = W1[t]; sTM[t] = g_tmat[b * 9 + t]; }
    if (t < 3)  { sS1[t] = s1[t]; sB1[t] = b1[t]; }
    __syncthreads();

    int gp = gp0 + t;
    int n  = gp & (NN - 1);

    // f_xyz = relu(((xyz @ t3x3) @ W1) * s1 + b1)
    float x0 = xyz[gp * 3 + 0], x1 = xyz[gp * 3 + 1], x2 = xyz[gp * 3 + 2];
    float v0 = x0 * sTM[0] + x1 * sTM[3] + x2 * sTM[6];
    float v1 = x0 * sTM[1] + x1 * sTM[4] + x2 * sTM[7];
    float v2 = x0 * sTM[2] + x1 * sTM[5] + x2 * sTM[8];
    float fx0 = fmaxf((v0 * sW1[0] + v1 * sW1[3] + v2 * sW1[6]) * sS1[0] + sB1[0], 0.f);
    float fx1 = fmaxf((v0 * sW1[1] + v1 * sW1[4] + v2 * sW1[7]) * sS1[1] + sB1[1], 0.f);
    float fx2 = fmaxf((v0 * sW1[2] + v1 * sW1[5] + v2 * sW1[8]) * sS1[2] + sB1[2], 0.f);

    // f_nei = relu((feat @ W2) * s2 + b2); feat read coalesced along n
    const float* fbase = feature + (size_t)b * DD * NN + n;
    float acc[32];
#pragma unroll
    for (int c = 0; c < 32; c++) acc[c] = 0.f;
#pragma unroll
    for (int i = 0; i < 32; i++) {
        float v = fbase[(size_t)i * NN];
#pragma unroll
        for (int c = 0; c < 32; c++) acc[c] += v * sW2[i * 32 + c];
    }
    float fn[32];
#pragma unroll
    for (int c = 0; c < 32; c++) fn[c] = fmaxf(acc[c] * sS2[c] + sB2[c], 0.f);

    // pre = relu((concat(fn, fx) @ W3) * s3 + b3)
#pragma unroll
    for (int c = 0; c < 32; c++) acc[c] = 0.f;
#pragma unroll
    for (int i = 0; i < 32; i++) {
        float v = fn[i];
#pragma unroll
        for (int c = 0; c < 32; c++) acc[c] += v * sW3[i * 32 + c];
    }
#pragma unroll
    for (int c = 0; c < 32; c++)
        acc[c] += fx0 * sW3[32 * 32 + c] + fx1 * sW3[33 * 32 + c] + fx2 * sW3[34 * 32 + c];
#pragma unroll
    for (int c = 0; c < 32; c++)
        stage[t * 33 + c] = fmaxf(acc[c] * sS3[c] + sB3[c], 0.f);
    __syncthreads();

    // coalesced write of [256 points x 32 ch] block
    float* outp = (float*)g_pre4 + (size_t)gp0 * 32;
    for (int i = t; i < 256 * 32; i += 256)
        outp[i] = stage[(i >> 5) * 33 + (i & 31)];
}

// ---------------------------------------------------------------------------
// K4: gather-max over K neighbors (8 lanes cooperate per point -> each gather
// touches exactly one 128B L2 line), then final 64->32 MLP.
// ---------------------------------------------------------------------------
__global__ void __launch_bounds__(256) k_gather_final(
    const float* __restrict__ feature, const int* __restrict__ nidx,
    const float* __restrict__ W4, const float* __restrict__ s4, const float* __restrict__ b4,
    float* __restrict__ out)
{
    __shared__ float sW4[2048], sS4[32], sB4[32];
    __shared__ float featS[32 * 36];     // 36-float rows: float4-aligned + low conflicts
    __shared__ float fcatS[32 * 36];
    int t = threadIdx.x;
    for (int i = t; i < 2048; i += 256) sW4[i] = W4[i];
    if (t < 32) { sS4[t] = s4[t]; sB4[t] = b4[t]; }

    int gp0 = blockIdx.x * 32;           // 32 points per block
    int b   = gp0 >> 16;
    int n0  = gp0 & (NN - 1);

    // stage feat (coalesced along n)
    const float* fbase = feature + (size_t)b * DD * NN + n0;
    for (int i = t; i < 1024; i += 256) {
        int c = i >> 5, p = i & 31;
        featS[p * 36 + c] = fbase[(size_t)c * NN + p];
    }

    // cooperative gather-max: 8 lanes per point, lane cl owns channels [4cl,4cl+4)
    int lane = t & 31;
    int warp = t >> 5;
    int cl   = lane & 7;
    int p    = warp * 4 + (lane >> 3);
    int gp   = gp0 + p;
    int mul  = g_idx64 ? 2 : 1;          // int64 -> read low 32-bit word
    const int* ib = nidx + (size_t)gp * KK * mul;
    int j0 = ib[cl * mul];
    int j1 = ib[(cl + 8) * mul];
    const float4* pre4 = g_pre4 + (size_t)b * NN * 8;
    float4 acc = make_float4(0.f, 0.f, 0.f, 0.f);   // pre >= 0 (ReLU), so 0-init exact
#pragma unroll
    for (int k = 0; k < KK; k++) {
        int j = __shfl_sync(0xffffffffu, (k < 8) ? j0 : j1, k & 7, 8);
        float4 v = pre4[(size_t)j * 8 + cl];
        acc.x = fmaxf(acc.x, v.x); acc.y = fmaxf(acc.y, v.y);
        acc.z = fmaxf(acc.z, v.z); acc.w = fmaxf(acc.w, v.w);
    }
    ((float4*)(fcatS + p * 36))[cl] = acc;
    __syncthreads();

    // final MLP: 8 threads per point, each computes 4 output channels
    int pp = t >> 3, g = t & 7;
    const float4* fS  = (const float4*)(featS + pp * 36);
    const float4* cS  = (const float4*)(fcatS + pp * 36);
    const float4* W44 = (const float4*)sW4;
    float4 a4 = make_float4(0.f, 0.f, 0.f, 0.f);
#pragma unroll
    for (int i4 = 0; i4 < 8; i4++) {
        float4 f = fS[i4];
        float4 w;
        w = W44[(i4 * 4 + 0) * 8 + g]; a4.x += f.x * w.x; a4.y += f.x * w.y; a4.z += f.x * w.z; a4.w += f.x * w.w;
        w = W44[(i4 * 4 + 1) * 8 + g]; a4.x += f.y * w.x; a4.y += f.y * w.y; a4.z += f.y * w.z; a4.w += f.y * w.w;
        w = W44[(i4 * 4 + 2) * 8 + g]; a4.x += f.z * w.x; a4.y += f.z * w.y; a4.z += f.z * w.z; a4.w += f.z * w.w;
        w = W44[(i4 * 4 + 3) * 8 + g]; a4.x += f.w * w.x; a4.y += f.w * w.y; a4.z += f.w * w.z; a4.w += f.w * w.w;
    }
#pragma unroll
    for (int i4 = 0; i4 < 8; i4++) {
        float4 f = cS[i4];
        float4 w;
        w = W44[(32 + i4 * 4 + 0) * 8 + g]; a4.x += f.x * w.x; a4.y += f.x * w.y; a4.z += f.x * w.z; a4.w += f.x * w.w;
        w = W44[(32 + i4 * 4 + 1) * 8 + g]; a4.x += f.y * w.x; a4.y += f.y * w.y; a4.z += f.y * w.z; a4.w += f.y * w.w;
        w = W44[(32 + i4 * 4 + 2) * 8 + g]; a4.x += f.z * w.x; a4.y += f.z * w.y; a4.z += f.z * w.z; a4.w += f.z * w.w;
        w = W44[(32 + i4 * 4 + 3) * 8 + g]; a4.x += f.w * w.x; a4.y += f.w * w.y; a4.z += f.w * w.z; a4.w += f.w * w.w;
    }
    int c0 = g * 4;
    float* ob = out + (size_t)b * DD * NN + (n0 + pp);
    ob[(size_t)(c0 + 0) * NN] = fmaxf(a4.x * sS4[c0 + 0] + sB4[c0 + 0], 0.f);
    ob[(size_t)(c0 + 1) * NN] = fmaxf(a4.y * sS4[c0 + 1] + sB4[c0 + 1], 0.f);
    ob[(size_t)(c0 + 2) * NN] = fmaxf(a4.z * sS4[c0 + 2] + sB4[c0 + 2], 0.f);
    ob[(size_t)(c0 + 3) * NN] = fmaxf(a4.w * sS4[c0 + 3] + sB4[c0 + 3], 0.f);
}

// ---------------------------------------------------------------------------

extern "C" void kernel_launch(void* const* d_in, const int* in_sizes, int n_in,
                              void* d_out, int out_size) {
    const float* feature = (const float*)d_in[0];
    const float* xyz     = (const float*)d_in[1];
    const int*   nidx    = (const int*)d_in[2];
    const float* tW1 = (const float*)d_in[3];  const float* ts1 = (const float*)d_in[4];  const float* tb1 = (const float*)d_in[5];
    const float* tW2 = (const float*)d_in[6];  const float* ts2 = (const float*)d_in[7];  const float* tb2 = (const float*)d_in[8];
    const float* tW3 = (const float*)d_in[9];  const float* ts3 = (const float*)d_in[10]; const float* tb3 = (const float*)d_in[11];
    const float* tW4 = (const float*)d_in[12]; const float* tb4 = (const float*)d_in[13];
    const float* W1  = (const float*)d_in[14]; const float* s1  = (const float*)d_in[15]; const float* b1  = (const float*)d_in[16];
    const float* W2  = (const float*)d_in[17]; const float* s2  = (const float*)d_in[18]; const float* b2  = (const float*)d_in[19];
    const float* W3  = (const float*)d_in[20]; const float* s3  = (const float*)d_in[21]; const float* b3  = (const float*)d_in[22];
    const float* W4  = (const float*)d_in[23]; const float* s4  = (const float*)d_in[24]; const float* b4  = (const float*)d_in[25];
    float* out = (float*)d_out;

    k_init<<<1, 128>>>(nidx);
    k_tnet_reduce<<<(BB * NN) / 256, 256>>>(xyz, tW1, ts1, tb1, tW2, ts2, tb2);
    k_tnet_head<<<BB, 64>>>(tW3, ts3, tb3, tW4, tb4);
    k_pointwise<<<(BB * NN) / 256, 256>>>(feature, xyz, W1, s1, b1, W2, s2, b2, W3, s3, b3);
    k_gather_final<<<(BB * NN) / 32, 256>>>(feature, nidx, W4, s4, b4, out);
}

// round 2
// speedup vs baseline: 1.1462x; 1.1462x over previous
#include <cuda_runtime.h>

#define BB 2
#define NN 65536
#define KK 16
#define DD 32

// Scratch (device globals; no allocation allowed)
__device__ float4 g_pre4[BB * NN * 8];   // pre[b][n][32] as float4 rows (16 MB, L2-resident)
__device__ float  g_part[128 * 64];      // per-block TNet partial maxima
__device__ float  g_tmat[BB * 9];
__device__ int    g_idx64;               // 1 if neigh_idx is int64, else 0

// ---------------------------------------------------------------------------
// K1: TNet pointwise 3->16->64 + max over 4 points/thread + warp/block reduce.
// Writes per-block partial maxima (no atomics, no init kernel needed).
// 128 blocks x 256 threads x 4 points = 131072 points.
// ---------------------------------------------------------------------------
__global__ void __launch_bounds__(256) k_tnet_reduce(
    const float* __restrict__ xyz,
    const float* __restrict__ tW1, const float* __restrict__ ts1, const float* __restrict__ tb1,
    const float* __restrict__ tW2, const float* __restrict__ ts2, const float* __restrict__ tb2)
{
    __shared__ float4 sW2f4[256];                // 16 rows x 64 cols as float4
    __shared__ float  sW1[48], sS1[16], sB1[16], sS2[64], sB2[64];
    __shared__ float  warpmax[8][64];
    int t = threadIdx.x;
    sW2f4[t] = ((const float4*)tW2)[t];
    if (t < 48) sW1[t] = tW1[t];
    if (t < 16) { sS1[t] = ts1[t]; sB1[t] = tb1[t]; }
    if (t < 64) { sS2[t] = ts2[t]; sB2[t] = tb2[t]; }
    __syncthreads();

    float m[64];
#pragma unroll
    for (int c = 0; c < 64; c++) m[c] = 0.f;

    int base = blockIdx.x * 1024;
#pragma unroll
    for (int r = 0; r < 4; r++) {
        int gp = base + r * 256 + t;
        float x0 = xyz[gp * 3 + 0], x1 = xyz[gp * 3 + 1], x2 = xyz[gp * 3 + 2];
        float h1[16];
#pragma unroll
        for (int c = 0; c < 16; c++) {
            float a = x0 * sW1[c] + x1 * sW1[16 + c] + x2 * sW1[32 + c];
            h1[c] = fmaxf(a * sS1[c] + sB1[c], 0.f);
        }
        float h2[64];
#pragma unroll
        for (int c = 0; c < 64; c++) h2[c] = 0.f;
#pragma unroll
        for (int i = 0; i < 16; i++) {
            float v = h1[i];
#pragma unroll
            for (int c4 = 0; c4 < 16; c4++) {
                float4 w = sW2f4[i * 16 + c4];
                h2[c4 * 4 + 0] += v * w.x; h2[c4 * 4 + 1] += v * w.y;
                h2[c4 * 4 + 2] += v * w.z; h2[c4 * 4 + 3] += v * w.w;
            }
        }
#pragma unroll
        for (int c = 0; c < 64; c++)
            m[c] = fmaxf(m[c], fmaxf(h2[c] * sS2[c] + sB2[c], 0.f));
    }

#pragma unroll
    for (int c = 0; c < 64; c++) {
#pragma unroll
        for (int off = 16; off; off >>= 1)
            m[c] = fmaxf(m[c], __shfl_xor_sync(0xffffffffu, m[c], off));
    }
    int w = t >> 5, lane = t & 31;
    if (lane == 0) {
#pragma unroll
        for (int c = 0; c < 64; c++) warpmax[w][c] = m[c];
    }
    __syncthreads();
    if (t < 64) {
        float v = warpmax[0][t];
#pragma unroll
        for (int ww = 1; ww < 8; ww++) v = fmaxf(v, warpmax[ww][t]);
        g_part[blockIdx.x * 64 + t] = v;
    }
}

// ---------------------------------------------------------------------------
// K2: reduce partials, TNet head 64 -> 16 -> 9 (+identity); idx dtype detect.
// ---------------------------------------------------------------------------
__global__ void k_tnet_head(
    const float* __restrict__ tW3, const float* __restrict__ ts3, const float* __restrict__ tb3,
    const float* __restrict__ tW4, const float* __restrict__ tb4,
    const int* __restrict__ nidx)
{
    __shared__ float hmax[64], h3s[16];
    int b = blockIdx.x, t = threadIdx.x;
    if (t < 64) {
        float v = 0.f;
        for (int j = 0; j < 64; j++) v = fmaxf(v, g_part[(b * 64 + j) * 64 + t]);
        hmax[t] = v;
    }
    __syncthreads();
    if (t < 16) {
        float a = 0.f;
        for (int i = 0; i < 64; i++) a += hmax[i] * tW3[i * 16 + t];
        h3s[t] = fmaxf(a * ts3[t] + tb3[t], 0.f);
    }
    __syncthreads();
    if (t < 9) {
        float a = 0.f;
        for (int i = 0; i < 16; i++) a += h3s[i] * tW4[i * 9 + t];
        a += tb4[t];
        if (t == 0 || t == 4 || t == 8) a += 1.0f;   // + eye(3)
        g_tmat[b * 9 + t] = a;
    }
    if (b == 0 && t == 63) {
        int z = 0;
#pragma unroll
        for (int i = 1; i < 16; i += 2) z |= nidx[i];
        g_idx64 = (z == 0) ? 1 : 0;
    }
}

// ---------------------------------------------------------------------------
// K3: fused per-point MLPs -> pre[b,n,32]. All weight reads are LDS.128.
// 1024 blocks x 128 threads, 1 point/thread.
// pre = relu((concat(f_nei, f_xyz) @ W3) * s3 + b3) moved OUT of the K loop.
// ---------------------------------------------------------------------------
__global__ void __launch_bounds__(128) k_pointwise(
    const float* __restrict__ feature, const float* __restrict__ xyz,
    const float* __restrict__ W1, const float* __restrict__ s1, const float* __restrict__ b1,
    const float* __restrict__ W2, const float* __restrict__ s2, const float* __restrict__ b2,
    const float* __restrict__ W3, const float* __restrict__ s3, const float* __restrict__ b3)
{
    __shared__ float4 sW2f4[256];        // W2 32x32
    __shared__ float4 sW3f4[256];        // W3 rows 0..31
    __shared__ float4 sW3x4[24];         // W3 rows 32..34 (xyz part)
    __shared__ float  sS2[32], sB2[32], sS3[32], sB3[32];
    __shared__ float  sW1[9], sTM[9], sS1[3], sB1[3];
    __shared__ float4 stage4[128 * 9];   // per-point rows, stride 9 f4 (36 floats)
    int t   = threadIdx.x;
    int gp0 = blockIdx.x * 128;
    int b   = gp0 >> 16;
    { const float4* W2v = (const float4*)W2;
      sW2f4[t] = W2v[t]; sW2f4[128 + t] = W2v[128 + t]; }
    { const float4* W3v = (const float4*)W3;
      sW3f4[t] = W3v[t]; sW3f4[128 + t] = W3v[128 + t];
      if (t < 24) sW3x4[t] = W3v[256 + t]; }
    if (t < 32) { sS2[t] = s2[t]; sB2[t] = b2[t]; sS3[t] = s3[t]; sB3[t] = b3[t]; }
    if (t < 9)  { sW1[t] = W1[t]; sTM[t] = g_tmat[b * 9 + t]; }
    if (t < 3)  { sS1[t] = s1[t]; sB1[t] = b1[t]; }
    __syncthreads();

    int gp = gp0 + t;
    int n  = gp & (NN - 1);

    // f_xyz = relu(((xyz @ t3x3) @ W1) * s1 + b1)
    float x0 = xyz[gp * 3 + 0], x1 = xyz[gp * 3 + 1], x2 = xyz[gp * 3 + 2];
    float v0 = x0 * sTM[0] + x1 * sTM[3] + x2 * sTM[6];
    float v1 = x0 * sTM[1] + x1 * sTM[4] + x2 * sTM[7];
    float v2 = x0 * sTM[2] + x1 * sTM[5] + x2 * sTM[8];
    float fx0 = fmaxf((v0 * sW1[0] + v1 * sW1[3] + v2 * sW1[6]) * sS1[0] + sB1[0], 0.f);
    float fx1 = fmaxf((v0 * sW1[1] + v1 * sW1[4] + v2 * sW1[7]) * sS1[1] + sB1[1], 0.f);
    float fx2 = fmaxf((v0 * sW1[2] + v1 * sW1[5] + v2 * sW1[8]) * sS1[2] + sB1[2], 0.f);

    // f_nei = relu((feat @ W2) * s2 + b2)
    const float* fbase = feature + (size_t)b * DD * NN + n;
    float acc[32];
#pragma unroll
    for (int c = 0; c < 32; c++) acc[c] = 0.f;
#pragma unroll
    for (int i = 0; i < 32; i++) {
        float v = fbase[(size_t)i * NN];
#pragma unroll
        for (int c4 = 0; c4 < 8; c4++) {
            float4 w = sW2f4[i * 8 + c4];
            acc[c4 * 4 + 0] += v * w.x; acc[c4 * 4 + 1] += v * w.y;
            acc[c4 * 4 + 2] += v * w.z; acc[c4 * 4 + 3] += v * w.w;
        }
    }
    float fn[32];
#pragma unroll
    for (int c = 0; c < 32; c++) fn[c] = fmaxf(acc[c] * sS2[c] + sB2[c], 0.f);

    // pre = relu((concat(fn, fx) @ W3) * s3 + b3)
#pragma unroll
    for (int c = 0; c < 32; c++) acc[c] = 0.f;
#pragma unroll
    for (int i = 0; i < 32; i++) {
        float v = fn[i];
#pragma unroll
        for (int c4 = 0; c4 < 8; c4++) {
            float4 w = sW3f4[i * 8 + c4];
            acc[c4 * 4 + 0] += v * w.x; acc[c4 * 4 + 1] += v * w.y;
            acc[c4 * 4 + 2] += v * w.z; acc[c4 * 4 + 3] += v * w.w;
        }
    }
#pragma unroll
    for (int c4 = 0; c4 < 8; c4++) {
        float4 wa = sW3x4[c4], wb = sW3x4[8 + c4], wc = sW3x4[16 + c4];
        acc[c4 * 4 + 0] += fx0 * wa.x + fx1 * wb.x + fx2 * wc.x;
        acc[c4 * 4 + 1] += fx0 * wa.y + fx1 * wb.y + fx2 * wc.y;
        acc[c4 * 4 + 2] += fx0 * wa.z + fx1 * wb.z + fx2 * wc.z;
        acc[c4 * 4 + 3] += fx0 * wa.w + fx1 * wb.w + fx2 * wc.w;
    }
#pragma unroll
    for (int c4 = 0; c4 < 8; c4++) {
        float4 o;
        o.x = fmaxf(acc[c4 * 4 + 0] * sS3[c4 * 4 + 0] + sB3[c4 * 4 + 0], 0.f);
        o.y = fmaxf(acc[c4 * 4 + 1] * sS3[c4 * 4 + 1] + sB3[c4 * 4 + 1], 0.f);
        o.z = fmaxf(acc[c4 * 4 + 2] * sS3[c4 * 4 + 2] + sB3[c4 * 4 + 2], 0.f);
        o.w = fmaxf(acc[c4 * 4 + 3] * sS3[c4 * 4 + 3] + sB3[c4 * 4 + 3], 0.f);
        stage4[t * 9 + c4] = o;
    }
    __syncthreads();

    // coalesced float4 writeout of [128 points x 32 ch]
    float4* out4 = (float4*)((float*)g_pre4 + (size_t)gp0 * 32);
#pragma unroll
    for (int r = 0; r < 8; r++) {
        int i = r * 128 + t;             // i = p*8 + c4
        out4[i] = stage4[i + (i >> 3)];  // p*9 + c4
    }
}

// ---------------------------------------------------------------------------
// K4: gather-max over K neighbors (8 lanes/point -> one 128B line per gather),
// then final 64->32 MLP. 64 points/block, 512 threads, coalesced output.
// ---------------------------------------------------------------------------
__global__ void __launch_bounds__(512) k_gather_final(
    const float* __restrict__ feature, const int* __restrict__ nidx,
    const float* __restrict__ W4, const float* __restrict__ s4, const float* __restrict__ b4,
    float* __restrict__ out)
{
    __shared__ float4 sW4f4[512];        // W4 64x32
    __shared__ float  sS4[32], sB4[32];
    __shared__ float4 featS4[64 * 9];    // feat rows, stride 9 f4
    __shared__ float4 fcatS4[64 * 9];    // max-pooled rows
    __shared__ float  sOut[64 * 33];     // output stage, stride 33
    int t = threadIdx.x;
    sW4f4[t] = ((const float4*)W4)[t];
    if (t < 32) { sS4[t] = s4[t]; sB4[t] = b4[t]; }

    int gp0 = blockIdx.x * 64;           // 64 points per block
    int b   = gp0 >> 16;
    int n0  = gp0 & (NN - 1);

    // stage feat (coalesced along n)
    const float* fbase = feature + (size_t)b * DD * NN + n0;
    float* featSf = (float*)featS4;
#pragma unroll
    for (int r = 0; r < 4; r++) {
        int i = r * 512 + t;             // i = c*64 + p
        int c = i >> 6, p = i & 63;
        featSf[p * 36 + c] = fbase[(size_t)c * NN + p];
    }

    // cooperative gather-max: 8 lanes per point, lane cl owns channels [4cl,4cl+4)
    int lane = t & 31;
    int warp = t >> 5;
    int cl   = lane & 7;
    int p    = warp * 4 + (lane >> 3);
    int gp   = gp0 + p;
    int mul  = g_idx64 ? 2 : 1;          // int64 -> read low 32-bit word
    const int* ib = nidx + (size_t)gp * KK * mul;
    int j0 = ib[cl * mul];
    int j1 = ib[(cl + 8) * mul];
    const float4* pre4 = g_pre4 + (size_t)b * NN * 8;
    float4 acc = make_float4(0.f, 0.f, 0.f, 0.f);   // pre >= 0 (ReLU), 0-init exact
#pragma unroll
    for (int k = 0; k < KK; k++) {
        int j = __shfl_sync(0xffffffffu, (k < 8) ? j0 : j1, k & 7, 8);
        float4 v = pre4[(size_t)j * 8 + cl];
        acc.x = fmaxf(acc.x, v.x); acc.y = fmaxf(acc.y, v.y);
        acc.z = fmaxf(acc.z, v.z); acc.w = fmaxf(acc.w, v.w);
    }
    fcatS4[p * 9 + cl] = acc;
    __syncthreads();

    // final MLP: 8 threads per point, each computes 4 output channels
    int pp = t >> 3, g = t & 7;
    const float4* fS = featS4 + pp * 9;
    const float4* cS = fcatS4 + pp * 9;
    float4 a4 = make_float4(0.f, 0.f, 0.f, 0.f);
#pragma unroll
    for (int i4 = 0; i4 < 8; i4++) {
        float4 f = fS[i4];
        float4 w;
        w = sW4f4[(i4 * 4 + 0) * 8 + g]; a4.x += f.x * w.x; a4.y += f.x * w.y; a4.z += f.x * w.z; a4.w += f.x * w.w;
        w = sW4f4[(i4 * 4 + 1) * 8 + g]; a4.x += f.y * w.x; a4.y += f.y * w.y; a4.z += f.y * w.z; a4.w += f.y * w.w;
        w = sW4f4[(i4 * 4 + 2) * 8 + g]; a4.x += f.z * w.x; a4.y += f.z * w.y; a4.z += f.z * w.z; a4.w += f.z * w.w;
        w = sW4f4[(i4 * 4 + 3) * 8 + g]; a4.x += f.w * w.x; a4.y += f.w * w.y; a4.z += f.w * w.z; a4.w += f.w * w.w;
    }
#pragma unroll
    for (int i4 = 0; i4 < 8; i4++) {
        float4 f = cS[i4];
        float4 w;
        w = sW4f4[(32 + i4 * 4 + 0) * 8 + g]; a4.x += f.x * w.x; a4.y += f.x * w.y; a4.z += f.x * w.z; a4.w += f.x * w.w;
        w = sW4f4[(32 + i4 * 4 + 1) * 8 + g]; a4.x += f.y * w.x; a4.y += f.y * w.y; a4.z += f.y * w.z; a4.w += f.y * w.w;
        w = sW4f4[(32 + i4 * 4 + 2) * 8 + g]; a4.x += f.z * w.x; a4.y += f.z * w.y; a4.z += f.z * w.z; a4.w += f.z * w.w;
        w = sW4f4[(32 + i4 * 4 + 3) * 8 + g]; a4.x += f.w * w.x; a4.y += f.w * w.y; a4.z += f.w * w.z; a4.w += f.w * w.w;
    }
    int c0 = g * 4;
    sOut[pp * 33 + c0 + 0] = fmaxf(a4.x * sS4[c0 + 0] + sB4[c0 + 0], 0.f);
    sOut[pp * 33 + c0 + 1] = fmaxf(a4.y * sS4[c0 + 1] + sB4[c0 + 1], 0.f);
    sOut[pp * 33 + c0 + 2] = fmaxf(a4.z * sS4[c0 + 2] + sB4[c0 + 2], 0.f);
    sOut[pp * 33 + c0 + 3] = fmaxf(a4.w * sS4[c0 + 3] + sB4[c0 + 3], 0.f);
    __syncthreads();

    // coalesced writeout
    float* ob = out + (size_t)b * DD * NN + n0;
#pragma unroll
    for (int r = 0; r < 4; r++) {
        int i = r * 512 + t;             // i = c*64 + p
        int c = i >> 6, pw = i & 63;
        ob[(size_t)c * NN + pw] = sOut[pw * 33 + c];
    }
}

// ---------------------------------------------------------------------------

extern "C" void kernel_launch(void* const* d_in, const int* in_sizes, int n_in,
                              void* d_out, int out_size) {
    const float* feature = (const float*)d_in[0];
    const float* xyz     = (const float*)d_in[1];
    const int*   nidx    = (const int*)d_in[2];
    const float* tW1 = (const float*)d_in[3];  const float* ts1 = (const float*)d_in[4];  const float* tb1 = (const float*)d_in[5];
    const float* tW2 = (const float*)d_in[6];  const float* ts2 = (const float*)d_in[7];  const float* tb2 = (const float*)d_in[8];
    const float* tW3 = (const float*)d_in[9];  const float* ts3 = (const float*)d_in[10]; const float* tb3 = (const float*)d_in[11];
    const float* tW4 = (const float*)d_in[12]; const float* tb4 = (const float*)d_in[13];
    const float* W1  = (const float*)d_in[14]; const float* s1  = (const float*)d_in[15]; const float* b1  = (const float*)d_in[16];
    const float* W2  = (const float*)d_in[17]; const float* s2  = (const float*)d_in[18]; const float* b2  = (const float*)d_in[19];
    const float* W3  = (const float*)d_in[20]; const float* s3  = (const float*)d_in[21]; const float* b3  = (const float*)d_in[22];
    const float* W4  = (const float*)d_in[23]; const float* s4  = (const float*)d_in[24]; const float* b4  = (const float*)d_in[25];
    float* out = (float*)d_out;

    k_tnet_reduce<<<128, 256>>>(xyz, tW1, ts1, tb1, tW2, ts2, tb2);
    k_tnet_head<<<BB, 64>>>(tW3, ts3, tb3, tW4, tb4, nidx);
    k_pointwise<<<(BB * NN) / 128, 128>>>(feature, xyz, W1, s1, b1, W2, s2, b2, W3, s3, b3);
    k_gather_final<<<(BB * NN) / 64, 512>>>(feature, nidx, W4, s4, b4, out);
}